// round 12
// baseline (speedup 1.0000x reference)
#include <cuda_runtime.h>
#include <cstdint>

#define B_SZ 1024
#define N_SZ 256
#define D_SZ 256
#define M_SZ 768
#define NEG_VAL -1.0e10f

// Scratch (__device__ globals; no allocation allowed)
// tf32-bit buffers (uint32) feed the tensor-core GEMMs directly.
__device__ uint32_t g_att[B_SZ * M_SZ];           // attention output, tf32 bits
__device__ uint32_t g_x[B_SZ * (M_SZ + D_SZ)];    // [LN(h), src], tf32 bits
__device__ uint32_t g_y[B_SZ * M_SZ];             // relu(x@W1^T), tf32 bits
__device__ float    g_part[3 * B_SZ * M_SZ];      // split-K partials (fp32)
#define WF_OFF  0
#define W1_OFF  (M_SZ * M_SZ)                      // 589824
#define W2_OFF  (W1_OFF + M_SZ * (M_SZ + D_SZ))    // +786432 = 1376256
#define W_TOT   (W2_OFF + D_SZ * M_SZ)             // +196608 = 1572864
__device__ uint32_t g_wtf[W_TOT];                  // all weights, tf32 bits

__device__ __forceinline__ uint32_t f2tf32(float x) {
    uint32_t r; asm("cvt.rna.tf32.f32 %0, %1;\n" : "=r"(r) : "f"(x)); return r;
}

// ---------------------------------------------------------------------------
// K0: one-shot weight conversion fp32 -> tf32 bits (vectorized).
// ---------------------------------------------------------------------------
__global__ __launch_bounds__(256) void cvt_w_kernel(
    const float4* __restrict__ fc_w, const float4* __restrict__ w1,
    const float4* __restrict__ w2)
{
    const int i = blockIdx.x * 256 + threadIdx.x;    // float4 index, 0..393215
    const float4* src; int off; uint32_t* dst;
    if (i < W1_OFF / 4)          { src = fc_w; off = i;              dst = g_wtf + WF_OFF; }
    else if (i < W2_OFF / 4)     { src = w1;   off = i - W1_OFF / 4; dst = g_wtf + W1_OFF; }
    else                         { src = w2;   off = i - W2_OFF / 4; dst = g_wtf + W2_OFF; }
    float4 v = __ldg(src + off);
    uint4 u = make_uint4(f2tf32(v.x), f2tf32(v.y), f2tf32(v.z), f2tf32(v.w));
    *(uint4*)(dst + off * 4) = u;
}

// ---------------------------------------------------------------------------
// K1: fused single-pass attention (unchanged math; epilogue stores tf32 bits).
// ---------------------------------------------------------------------------
#define TROWS 8
#define ATTN_SMEM ((2 * TROWS * M_SZ + N_SZ + TROWS + 12 + 64) * 4)

__device__ __forceinline__ void cp_async16(uint32_t saddr, const void* gaddr) {
    asm volatile("cp.async.cg.shared.global [%0], [%1], 16;\n" :: "r"(saddr), "l"(gaddr));
}
__device__ __forceinline__ void cp_commit() { asm volatile("cp.async.commit_group;\n"); }

__global__ __launch_bounds__(256) void attn_kernel(
    const float* __restrict__ seq, const float* __restrict__ seq_e,
    const float* __restrict__ seq_t, const unsigned int* __restrict__ mask,
    const float* __restrict__ shared_attn, float* __restrict__ attn_w_out)
{
    extern __shared__ float smem[];
    float* sK    = smem;                        // [2][TROWS][768]
    float* s_all = smem + 2 * TROWS * M_SZ;     // [256]
    float* ts    = s_all + N_SZ;                // [TROWS]
    float* sp    = ts + TROWS;                  // [TROWS + 1]
    float* sPP   = sp + TROWS + 4;              // [8 warps][8 rows]

    const int b    = blockIdx.x;
    const int tid  = threadIdx.x;
    const int lane = tid & 31;
    const int wrp  = tid >> 5;
    const size_t bbase = (size_t)b * N_SZ * D_SZ;

    const float wk0 = __ldg(shared_attn + M_SZ + 2 * tid);
    const float wk1 = __ldg(shared_attn + M_SZ + 2 * tid + 1);
    const float wk2 = __ldg(shared_attn + M_SZ + 512 + tid);

    float2 a01 = make_float2(0.f, 0.f);
    float  a2  = 0.f;
    float lsum = 0.f, mval = -3.0e38f;

    {
        #pragma unroll
        for (int u = 0; u < 6; u++) {
            int idx = u * 256 + tid;
            int r   = idx / 192;
            int pos = idx - r * 192;
            int seg = pos >> 6;
            int j4  = pos & 63;
            const float* base = (seg == 0) ? seq : ((seg == 1) ? seq_e : seq_t);
            uint32_t sa = (uint32_t)__cvta_generic_to_shared(sK + (r * 192 + pos) * 4);
            cp_async16(sa, base + bbase + (size_t)r * D_SZ + j4 * 4);
        }
        cp_commit();
    }

    for (int t = 0; t < N_SZ / TROWS; t++) {
        const int cur = t & 1;
        if (t + 1 < N_SZ / TROWS) {
            const int nxt = (t + 1) & 1;
            const int n0n = (t + 1) * TROWS;
            #pragma unroll
            for (int u = 0; u < 6; u++) {
                int idx = u * 256 + tid;
                int r   = idx / 192;
                int pos = idx - r * 192;
                int seg = pos >> 6;
                int j4  = pos & 63;
                const float* base = (seg == 0) ? seq : ((seg == 1) ? seq_e : seq_t);
                uint32_t sa = (uint32_t)__cvta_generic_to_shared(
                    sK + (nxt * TROWS * M_SZ) + (r * 192 + pos) * 4);
                cp_async16(sa, base + bbase + (size_t)(n0n + r) * D_SZ + j4 * 4);
            }
            cp_commit();
            asm volatile("cp.async.wait_group 1;\n");
        } else {
            asm volatile("cp.async.wait_group 0;\n");
        }
        __syncthreads();                        // sync1: tile visible

        const float* kb = sK + cur * TROWS * M_SZ;
        const int n0 = t * TROWS;

        float2 kv2[TROWS];
        float  kv1[TROWS];
        float  v[TROWS];
        #pragma unroll
        for (int r = 0; r < TROWS; r++) {
            const float* kr = kb + r * M_SZ;
            kv2[r] = *(const float2*)(kr + 2 * tid);
            kv1[r] = kr[512 + tid];
            v[r] = kv2[r].x * wk0 + kv2[r].y * wk1 + kv1[r] * wk2;
        }

        {
            float w4[4];
            const bool h16 = (lane & 16) != 0;
            #pragma unroll
            for (int j = 0; j < 4; j++) {
                float snd = h16 ? v[j] : v[j + 4];
                float rc  = __shfl_xor_sync(0xffffffffu, snd, 16);
                w4[j] = (h16 ? v[j + 4] : v[j]) + rc;
            }
            float w2r[2];
            const bool h8 = (lane & 8) != 0;
            #pragma unroll
            for (int j = 0; j < 2; j++) {
                float snd = h8 ? w4[j] : w4[j + 2];
                float rc  = __shfl_xor_sync(0xffffffffu, snd, 8);
                w2r[j] = (h8 ? w4[j + 2] : w4[j]) + rc;
            }
            const bool h4 = (lane & 4) != 0;
            float snd = h4 ? w2r[0] : w2r[1];
            float rc  = __shfl_xor_sync(0xffffffffu, snd, 4);
            float y   = (h4 ? w2r[1] : w2r[0]) + rc;
            y += __shfl_xor_sync(0xffffffffu, y, 2);
            y += __shfl_xor_sync(0xffffffffu, y, 1);
            if ((lane & 3) == 0) sPP[wrp * 8 + (lane >> 2)] = y;
        }
        __syncthreads();                        // sync2: partials visible

        if (wrp == 0 && lane < TROWS) {
            float tot = 0.f;
            #pragma unroll
            for (int w = 0; w < 8; w++) tot += sPP[w * 8 + lane];
            int n = n0 + lane;
            float s = (mask[(size_t)b * N_SZ + n] != 0u) ? NEG_VAL : tot;
            ts[lane]  = s;
            s_all[n]  = s;
        }
        __syncthreads();                        // sync3: ts visible

        float mt = mval;
        #pragma unroll
        for (int r = 0; r < TROWS; r++) mt = fmaxf(mt, ts[r]);

        if (wrp == 0) {
            float pv = (lane < TROWS) ? __expf(ts[lane] - mt) : 0.f;
            float tot = pv;
            #pragma unroll
            for (int o = 16; o > 0; o >>= 1) tot += __shfl_xor_sync(0xffffffffu, tot, o);
            if (lane < TROWS) sp[lane] = pv;
            if (lane == 0)    sp[TROWS] = tot;
        }
        if (mt > mval) {
            float sc = __expf(mval - mt);
            a01.x *= sc; a01.y *= sc; a2 *= sc; lsum *= sc;
            mval = mt;
        }
        __syncthreads();                        // sync4: sp visible

        lsum += sp[TROWS];
        #pragma unroll
        for (int r = 0; r < TROWS; r++) {
            float p = sp[r];
            a01.x = fmaf(p, kv2[r].x, a01.x);
            a01.y = fmaf(p, kv2[r].y, a01.y);
            a2    = fmaf(p, kv1[r],   a2);
        }
    }

    float inv = 1.0f / lsum;
    attn_w_out[(size_t)b * N_SZ + tid] = __expf(s_all[tid] - mval) * inv;
    uint32_t* o = g_att + (size_t)b * M_SZ;
    *(uint2*)(o + 2 * tid) = make_uint2(f2tf32(a01.x * inv), f2tf32(a01.y * inv));
    o[512 + tid] = f2tf32(a2 * inv);
}

// ---------------------------------------------------------------------------
// Split-K tf32 tensor-core GEMM, operands pre-converted to tf32 bits.
// 2-stage cp.async double-buffered staging (no cvt, no register prefetch);
// __launch_bounds__(256,3) for 3 CTAs/SM.
// ---------------------------------------------------------------------------
__device__ __forceinline__ void mma_tf32(float* c, const uint32_t* a, const uint32_t* b) {
    asm volatile(
        "mma.sync.aligned.m16n8k8.row.col.f32.tf32.tf32.f32 "
        "{%0,%1,%2,%3}, {%4,%5,%6,%7}, {%8,%9}, {%0,%1,%2,%3};\n"
        : "+f"(c[0]), "+f"(c[1]), "+f"(c[2]), "+f"(c[3])
        : "r"(a[0]), "r"(a[1]), "r"(a[2]), "r"(a[3]), "r"(b[0]), "r"(b[1]));
}

#define GEMM_SMEM (2 * (128 + 64) * 36 * 4)

template <int KD, int S>
__global__ __launch_bounds__(256, 3) void gemm_tc_kernel(
    const uint32_t* __restrict__ A, const uint32_t* __restrict__ W,
    float* __restrict__ part, int Nout)
{
    extern __shared__ __align__(16) uint32_t dsm[];
    uint32_t* sAb = dsm;                        // [2][128*36]
    uint32_t* sWb = dsm + 2 * 128 * 36;         // [2][64*36]

    const int tid  = threadIdx.x;
    const int wid  = tid >> 5, lane = tid & 31;
    const int g    = lane >> 2, tg = lane & 3;
    const int wm   = wid & 1,  wn  = wid >> 1;
    const int m0   = blockIdx.x * 128;
    const int n0   = blockIdx.y * 64;
    const int z    = blockIdx.z;
    constexpr int KT = KD / 32;
    const int kt0 = z * KT / S;
    const int kt1 = (z + 1) * KT / S;

    const int ra_r = tid >> 3, ra_j = tid & 7;

    // stage issue helper
    auto issue_tile = [&](int kt, int buf) {
        const int kc = kt * 32;
        uint32_t* sa = sAb + buf * 128 * 36;
        uint32_t* sw = sWb + buf * 64 * 36;
        #pragma unroll
        for (int u = 0; u < 4; u++) {
            uint32_t da = (uint32_t)__cvta_generic_to_shared(sa + (u * 32 + ra_r) * 36 + ra_j * 4);
            cp_async16(da, A + (size_t)(m0 + u * 32 + ra_r) * KD + kc + ra_j * 4);
        }
        #pragma unroll
        for (int u = 0; u < 2; u++) {
            uint32_t dw = (uint32_t)__cvta_generic_to_shared(sw + (u * 32 + ra_r) * 36 + ra_j * 4);
            cp_async16(dw, W + (size_t)(n0 + u * 32 + ra_r) * KD + kc + ra_j * 4);
        }
        cp_commit();
    };

    float acc[4][2][4];
    #pragma unroll
    for (int mi = 0; mi < 4; mi++)
        #pragma unroll
        for (int ni = 0; ni < 2; ni++)
            #pragma unroll
            for (int f = 0; f < 4; f++) acc[mi][ni][f] = 0.f;

    issue_tile(kt0, 0);

    for (int kt = kt0; kt < kt1; kt++) {
        const int cur = (kt - kt0) & 1;
        if (kt + 1 < kt1) {
            issue_tile(kt + 1, cur ^ 1);
            asm volatile("cp.async.wait_group 1;\n");
        } else {
            asm volatile("cp.async.wait_group 0;\n");
        }
        __syncthreads();                        // buf cur visible

        const uint32_t* sA = sAb + cur * 128 * 36;
        const uint32_t* sW = sWb + cur * 64 * 36;

        #pragma unroll
        for (int ks = 0; ks < 4; ks++) {
            const int kb = ks * 8;
            uint32_t bfrag[2][2];
            #pragma unroll
            for (int ni = 0; ni < 2; ni++) {
                const int n = wn * 16 + ni * 8;
                bfrag[ni][0] = sW[(n + g) * 36 + kb + tg];
                bfrag[ni][1] = sW[(n + g) * 36 + kb + tg + 4];
            }
            #pragma unroll
            for (int mi = 0; mi < 4; mi++) {
                const int m = wm * 64 + mi * 16;
                uint32_t afrag[4];
                afrag[0] = sA[(m + g)     * 36 + kb + tg];
                afrag[1] = sA[(m + g + 8) * 36 + kb + tg];
                afrag[2] = sA[(m + g)     * 36 + kb + tg + 4];
                afrag[3] = sA[(m + g + 8) * 36 + kb + tg + 4];
                #pragma unroll
                for (int ni = 0; ni < 2; ni++)
                    mma_tf32(acc[mi][ni], afrag, bfrag[ni]);
            }
        }
        __syncthreads();                        // all reads done before overwrite
    }

    float* p = part + (size_t)z * B_SZ * Nout;
    #pragma unroll
    for (int mi = 0; mi < 4; mi++) {
        const int m = m0 + wm * 64 + mi * 16;
        #pragma unroll
        for (int ni = 0; ni < 2; ni++) {
            const int n = n0 + wn * 16 + ni * 8 + tg * 2;
            *(float2*)(p + (size_t)(m + g)     * Nout + n) = make_float2(acc[mi][ni][0], acc[mi][ni][1]);
            *(float2*)(p + (size_t)(m + g + 8) * Nout + n) = make_float2(acc[mi][ni][2], acc[mi][ni][3]);
        }
    }
}

// ---------------------------------------------------------------------------
// Reduce kernels (fold split-K partials + epilogue); outputs tf32 bits where
// the consumer is a GEMM.
// ---------------------------------------------------------------------------
__global__ __launch_bounds__(256) void reduce_fc_ln_kernel(
    const float* __restrict__ src, const float* __restrict__ src_t,
    const float* __restrict__ ln_w, const float* __restrict__ ln_b)
{
    __shared__ float red[8];
    const int b = blockIdx.x;
    const int tid = threadIdx.x;
    const int lane = tid & 31, wrp = tid >> 5;

    const float* p0 = g_part + (size_t)b * M_SZ;
    const float* p1 = p0 + (size_t)B_SZ * M_SZ;
    const float* p2 = p1 + (size_t)B_SZ * M_SZ;

    float x0 = p0[tid]       + p1[tid]       + p2[tid]       + src[(size_t)b * D_SZ + tid];
    float x1 = p0[tid + 256] + p1[tid + 256] + p2[tid + 256];
    float x2 = p0[tid + 512] + p1[tid + 512] + p2[tid + 512] + src_t[(size_t)b * D_SZ + tid];

    float s = x0 + x1 + x2;
    #pragma unroll
    for (int o = 16; o > 0; o >>= 1) s += __shfl_xor_sync(0xffffffffu, s, o);
    if (lane == 0) red[wrp] = s;
    __syncthreads();
    float mu = (red[0]+red[1]+red[2]+red[3]+red[4]+red[5]+red[6]+red[7]) * (1.0f/768.0f);
    __syncthreads();

    float d0 = x0 - mu, d1 = x1 - mu, d2 = x2 - mu;
    float q = d0*d0 + d1*d1 + d2*d2;
    #pragma unroll
    for (int o = 16; o > 0; o >>= 1) q += __shfl_xor_sync(0xffffffffu, q, o);
    if (lane == 0) red[wrp] = q;
    __syncthreads();
    float var = (red[0]+red[1]+red[2]+red[3]+red[4]+red[5]+red[6]+red[7]) * (1.0f/768.0f);
    float rstd = rsqrtf(var + 1e-5f);

    uint32_t* xo = g_x + (size_t)b * (M_SZ + D_SZ);
    xo[tid]       = f2tf32(d0 * rstd * ln_w[tid]       + ln_b[tid]);
    xo[tid + 256] = f2tf32(d1 * rstd * ln_w[tid + 256] + ln_b[tid + 256]);
    xo[tid + 512] = f2tf32(d2 * rstd * ln_w[tid + 512] + ln_b[tid + 512]);
    xo[768 + tid] = f2tf32(src[(size_t)b * D_SZ + tid]);
}

__global__ __launch_bounds__(256) void reduce_relu_kernel()
{
    const int b = blockIdx.x;
    const int tid = threadIdx.x;
    const float* p0 = g_part + (size_t)b * M_SZ;
    const float* p1 = p0 + (size_t)B_SZ * M_SZ;
    const float* p2 = p1 + (size_t)B_SZ * M_SZ;
    uint32_t* y = g_y + (size_t)b * M_SZ;
    #pragma unroll
    for (int c = 0; c < 3; c++) {
        int f = tid + c * 256;
        y[f] = f2tf32(fmaxf(p0[f] + p1[f] + p2[f], 0.f));
    }
}

__global__ __launch_bounds__(256) void reduce_out_kernel(float* __restrict__ out)
{
    const int b = blockIdx.x;
    const int tid = threadIdx.x;
    float s = 0.f;
    #pragma unroll
    for (int z = 0; z < 8; z++)
        s += g_part[(size_t)z * B_SZ * D_SZ + (size_t)b * D_SZ + tid];
    out[(size_t)b * D_SZ + tid] = s;
}

// ---------------------------------------------------------------------------
extern "C" void kernel_launch(void* const* d_in, const int* in_sizes, int n_in,
                              void* d_out, int out_size)
{
    const float* src         = (const float*)d_in[0];
    const float* src_t       = (const float*)d_in[1];
    const float* seq         = (const float*)d_in[2];
    const float* seq_t       = (const float*)d_in[3];
    const float* seq_e       = (const float*)d_in[4];
    const unsigned int* mask = (const unsigned int*)d_in[5];
    const float* shared_attn = (const float*)d_in[6];
    const float* fc_w        = (const float*)d_in[7];
    const float* ln_w        = (const float*)d_in[8];
    const float* ln_b        = (const float*)d_in[9];
    const float* w1          = (const float*)d_in[10];
    const float* w2          = (const float*)d_in[11];

    float* out    = (float*)d_out;
    float* attn_w = out + (size_t)B_SZ * D_SZ;

    uint32_t* g_att_p; cudaGetSymbolAddress((void**)&g_att_p, g_att);
    uint32_t* g_x_p;   cudaGetSymbolAddress((void**)&g_x_p, g_x);
    uint32_t* g_y_p;   cudaGetSymbolAddress((void**)&g_y_p, g_y);
    float* g_part_p;   cudaGetSymbolAddress((void**)&g_part_p, g_part);
    uint32_t* g_wtf_p; cudaGetSymbolAddress((void**)&g_wtf_p, g_wtf);

    cudaFuncSetAttribute(attn_kernel, cudaFuncAttributeMaxDynamicSharedMemorySize, ATTN_SMEM);
    cudaFuncSetAttribute(gemm_tc_kernel<768, 3>,  cudaFuncAttributeMaxDynamicSharedMemorySize, GEMM_SMEM);
    cudaFuncSetAttribute(gemm_tc_kernel<1024, 3>, cudaFuncAttributeMaxDynamicSharedMemorySize, GEMM_SMEM);
    cudaFuncSetAttribute(gemm_tc_kernel<768, 8>,  cudaFuncAttributeMaxDynamicSharedMemorySize, GEMM_SMEM);

    cvt_w_kernel<<<W_TOT / 4 / 256, 256>>>((const float4*)fc_w, (const float4*)w1,
                                           (const float4*)w2);

    attn_kernel<<<B_SZ, 256, ATTN_SMEM>>>(seq, seq_e, seq_t, mask, shared_attn, attn_w);

    gemm_tc_kernel<768, 3><<<dim3(8, 12, 3), 256, GEMM_SMEM>>>(g_att_p, g_wtf_p + WF_OFF, g_part_p, M_SZ);
    reduce_fc_ln_kernel<<<B_SZ, 256>>>(src, src_t, ln_w, ln_b);

    gemm_tc_kernel<1024, 3><<<dim3(8, 12, 3), 256, GEMM_SMEM>>>(g_x_p, g_wtf_p + W1_OFF, g_part_p, M_SZ);
    reduce_relu_kernel<<<B_SZ, 256>>>();

    gemm_tc_kernel<768, 8><<<dim3(8, 4, 8), 256, GEMM_SMEM>>>(g_y_p, g_wtf_p + W2_OFF, g_part_p, D_SZ);
    reduce_out_kernel<<<B_SZ, 256>>>(out);
}